// round 13
// baseline (speedup 1.0000x reference)
#include <cuda_runtime.h>
#include <cuda_bf16.h>

// Problem: B=64, T=2048, H=256
//   energy[b,t] = q[b,t] . (W^T v)   [(b.v) cancels in softmax]
//   out = masked softmax; masked tokens exactly 0, never read.
//
// Structure: uc (primary) -> energy (PDL, q-loads issued before griddep wait)
// -> scale (PDL, per-ROW spin on release counters instead of grid-wide wait,
// so each row is normalized as soon as ITS energy blocks finish).

#define B_DIM 64
#define T_DIM 2048
#define H_DIM 256
#define TOK_PER_BLOCK 64
#define EBLOCKS_PER_ROW (T_DIM / TOK_PER_BLOCK)   // 32

// __device__ globals: zero-init at load; psum slots of masked chunks are
// NEVER written on any replay -> stay 0. Row counters self-reset in scale.
__device__ float g_u[H_DIM];
__device__ float g_exp[B_DIM * T_DIM];
__device__ float g_psum[B_DIM * EBLOCKS_PER_ROW];
__device__ unsigned int g_row_done[B_DIM];

// fire-and-forget release increment (no result -> no CTA dead time)
__device__ __forceinline__ void red_inc_release(unsigned int* p) {
    asm volatile("red.release.gpu.global.add.u32 [%0], 1;" :: "l"(p) : "memory");
}
__device__ __forceinline__ unsigned int ld_acquire(const unsigned int* p) {
    unsigned int v;
    asm volatile("ld.acquire.gpu.global.u32 %0, [%1];" : "=r"(v) : "l"(p) : "memory");
    return v;
}

// ---------------------------------------------------------------------------
// K0: u = W^T v, single phase. 64 blocks x 256 threads.
// ---------------------------------------------------------------------------
__global__ void __launch_bounds__(256) uc_kernel(const float* __restrict__ W,
                                                 const float* __restrict__ v) {
    __shared__ float4 red[256];   // 4KB
    int g = blockIdx.x;
    int k = threadIdx.x;

    float vk = __ldg(&v[k]);
    float4 w = __ldg(reinterpret_cast<const float4*>(W + k * H_DIM + 4 * g));
    red[k] = make_float4(vk * w.x, vk * w.y, vk * w.z, vk * w.w);
    __syncthreads();
#pragma unroll
    for (int off = 128; off > 32; off >>= 1) {
        if (k < off) {
            float4 a = red[k], b4 = red[k + off];
            red[k] = make_float4(a.x + b4.x, a.y + b4.y, a.z + b4.z, a.w + b4.w);
        }
        __syncthreads();
    }
    if (k < 32) {
        float4 a = red[k], b4 = red[k + 32];
        float sx = a.x + b4.x, sy = a.y + b4.y, sz = a.z + b4.z, sw = a.w + b4.w;
#pragma unroll
        for (int o = 16; o > 0; o >>= 1) {
            sx += __shfl_xor_sync(0xFFFFFFFFu, sx, o);
            sy += __shfl_xor_sync(0xFFFFFFFFu, sy, o);
            sz += __shfl_xor_sync(0xFFFFFFFFu, sz, o);
            sw += __shfl_xor_sync(0xFFFFFFFFu, sw, o);
        }
        if (k == 0)
            reinterpret_cast<float4*>(g_u)[g] = make_float4(sx, sy, sz, sw);
    }
}

// ---------------------------------------------------------------------------
// K1 (PDL secondary): 512 threads, 4 tokens/warp, 64 tok/block.
//   q loads issued BEFORE the griddep wait on uc. After psum store, one
//   fire-and-forget release increment on the row counter.
// ---------------------------------------------------------------------------
__global__ void __launch_bounds__(512) energy_exp_kernel(
        const float* __restrict__ q,
        const int* __restrict__ lens) {
    int b     = blockIdx.x >> 5;                 // / 32 blocks per row
    int chunk = blockIdx.x & 31;
    int t0    = chunk * TOK_PER_BLOCK;
    int len   = __ldg(&lens[b]);
    if (t0 >= len) return;                       // masked: no work, no arrival

    long rowbase = (long)b * T_DIM;
    int tid  = threadIdx.x;
    int warp = tid >> 5;
    int lane = tid & 31;

    __shared__ float red[TOK_PER_BLOCK];

    int tA = t0 + warp * 4;

    const float4* qp = reinterpret_cast<const float4*>(q + (rowbase + tA) * H_DIM)
                       + lane * 2;
    float4 z = {0.f, 0.f, 0.f, 0.f};
    float4 r0[4], r1[4];
    bool vld[4];
#pragma unroll
    for (int j = 0; j < 4; ++j) {
        vld[j] = (tA + j) < len;
        const float4* pj = qp + j * (H_DIM / 4);
        r0[j] = vld[j] ? __ldcs(pj)     : z;
        r1[j] = vld[j] ? __ldcs(pj + 1) : z;
    }

    cudaGridDependencySynchronize();             // uc complete; g_u visible

    float4 ua = __ldg(reinterpret_cast<const float4*>(g_u) + lane * 2);
    float4 ub = __ldg(reinterpret_cast<const float4*>(g_u) + lane * 2 + 1);

    float d[4];
#pragma unroll
    for (int j = 0; j < 4; ++j) {
        d[j] = r0[j].x * ua.x + r0[j].y * ua.y + r0[j].z * ua.z + r0[j].w * ua.w
             + r1[j].x * ub.x + r1[j].y * ub.y + r1[j].z * ub.z + r1[j].w * ub.w;
    }
#pragma unroll
    for (int o = 16; o > 0; o >>= 1) {
#pragma unroll
        for (int j = 0; j < 4; ++j) d[j] += __shfl_xor_sync(0xFFFFFFFFu, d[j], o);
    }

    if (lane == 0) {
#pragma unroll
        for (int j = 0; j < 4; ++j) {
            float e = vld[j] ? __expf(d[j]) : 0.f;
            __stcg(&g_exp[rowbase + tA + j], e);
            red[warp * 4 + j] = e;
        }
    }
    __syncthreads();
    if (tid == 0) {
        float s = 0.f;
#pragma unroll
        for (int w = 0; w < TOK_PER_BLOCK; ++w) s += red[w];  // fixed order
        g_psum[blockIdx.x] = s;
        red_inc_release(&g_row_done[b]);         // fire-and-forget
    }
}

// ---------------------------------------------------------------------------
// K2 (PDL secondary): 64 blocks x 512 threads. Thread 0 spins until this
//   row's ceil(len/64) energy blocks have released, then the block
//   normalizes its row. Counter reset for next graph replay.
// ---------------------------------------------------------------------------
__global__ void __launch_bounds__(512) scale_kernel(
        const int* __restrict__ lens,
        float* __restrict__ out) {
    int b    = blockIdx.x;
    int tid  = threadIdx.x;
    int lane = tid & 31;
    int len  = __ldg(&lens[b]);
    long rowbase = (long)b * T_DIM;

    unsigned int target = (unsigned int)((len + TOK_PER_BLOCK - 1) / TOK_PER_BLOCK);
    if (tid == 0) {
        while (ld_acquire(&g_row_done[b]) < target) { __nanosleep(64); }
    }
    __syncthreads();                             // row's psums now visible

    const float* ps = g_psum + b * EBLOCKS_PER_ROW;
    float s = __ldcg(&ps[lane]);                 // 32 psums/row; masked slots = 0
#pragma unroll
    for (int o = 16; o > 0; o >>= 1) s += __shfl_xor_sync(0xFFFFFFFFu, s, o);
    float inv = 1.0f / s;

    int tbase = tid * 4;
    float4* ob = reinterpret_cast<float4*>(out + rowbase);
    if (tbase >= len) {
        ob[tid] = make_float4(0.f, 0.f, 0.f, 0.f);
    } else {
        float4 val = __ldcg(&reinterpret_cast<const float4*>(g_exp + rowbase)[tid]);
        val.x = (tbase + 0 < len) ? val.x * inv : 0.f;
        val.y = (tbase + 1 < len) ? val.y * inv : 0.f;
        val.z = (tbase + 2 < len) ? val.z * inv : 0.f;
        val.w = (tbase + 3 < len) ? val.w * inv : 0.f;
        ob[tid] = val;
    }
    __syncthreads();
    if (tid == 0) g_row_done[b] = 0;             // reset for next graph replay
}

// ---------------------------------------------------------------------------
extern "C" void kernel_launch(void* const* d_in, const int* in_sizes, int n_in,
                              void* d_out, int out_size) {
    const float* questions = (const float*)d_in[0];   // [B,T,H] f32
    const int*   lens      = (const int*)d_in[1];     // [B] i32
    const float* W         = (const float*)d_in[2];   // [H,H] f32
    // d_in[3] = b (cancels in softmax)
    const float* v         = (const float*)d_in[4];   // [H] f32
    float* out             = (float*)d_out;           // [B,T] f32

    uc_kernel<<<H_DIM / 4, 256>>>(W, v);

    cudaLaunchAttribute attr[1];
    attr[0].id = cudaLaunchAttributeProgrammaticStreamSerialization;
    attr[0].val.programmaticStreamSerializationAllowed = 1;

    {
        cudaLaunchConfig_t cfg = {};
        cfg.gridDim  = dim3(B_DIM * EBLOCKS_PER_ROW);
        cfg.blockDim = dim3(512);
        cfg.attrs = attr;
        cfg.numAttrs = 1;
        cudaLaunchKernelEx(&cfg, energy_exp_kernel, questions, lens);
    }
    {
        cudaLaunchConfig_t cfg = {};
        cfg.gridDim  = dim3(B_DIM);
        cfg.blockDim = dim3(512);
        cfg.attrs = attr;
        cfg.numAttrs = 1;
        cudaLaunchKernelEx(&cfg, scale_kernel, lens, out);
    }
}

// round 14
// speedup vs baseline: 1.0399x; 1.0399x over previous
#include <cuda_runtime.h>
#include <cuda_bf16.h>

// Problem: B=64, T=2048, H=256
//   energy[b,t] = q[b,t] . (W^T v)   [(b.v) cancels in softmax]
//   out = masked softmax; masked tokens exactly 0, never read.
//
// Structure (R11, best known): uc primary -> energy PDL (q loads issued
// before griddep wait) -> scale PDL (griddep wait; per-row spin regressed in
// R12 and is reverted). R13 change: energy at 8 tok/warp, 256 thr/block,
// 16 front-batched LDG.128 per thread for max MLP.

#define B_DIM 64
#define T_DIM 2048
#define H_DIM 256
#define TOK_PER_BLOCK 64
#define EBLOCKS_PER_ROW (T_DIM / TOK_PER_BLOCK)   // 32

// __device__ globals: zero-init at load; psum slots of masked chunks are
// NEVER written on any replay -> stay 0, so scale sums unconditionally.
__device__ float g_u[H_DIM];
__device__ float g_exp[B_DIM * T_DIM];
__device__ float g_psum[B_DIM * EBLOCKS_PER_ROW];

// ---------------------------------------------------------------------------
// K0: u = W^T v, single phase. 64 blocks x 256 threads.
// ---------------------------------------------------------------------------
__global__ void __launch_bounds__(256) uc_kernel(const float* __restrict__ W,
                                                 const float* __restrict__ v) {
    __shared__ float4 red[256];   // 4KB
    int g = blockIdx.x;
    int k = threadIdx.x;

    float vk = __ldg(&v[k]);
    float4 w = __ldg(reinterpret_cast<const float4*>(W + k * H_DIM + 4 * g));
    red[k] = make_float4(vk * w.x, vk * w.y, vk * w.z, vk * w.w);
    __syncthreads();
#pragma unroll
    for (int off = 128; off > 32; off >>= 1) {
        if (k < off) {
            float4 a = red[k], b4 = red[k + off];
            red[k] = make_float4(a.x + b4.x, a.y + b4.y, a.z + b4.z, a.w + b4.w);
        }
        __syncthreads();
    }
    if (k < 32) {
        float4 a = red[k], b4 = red[k + 32];
        float sx = a.x + b4.x, sy = a.y + b4.y, sz = a.z + b4.z, sw = a.w + b4.w;
#pragma unroll
        for (int o = 16; o > 0; o >>= 1) {
            sx += __shfl_xor_sync(0xFFFFFFFFu, sx, o);
            sy += __shfl_xor_sync(0xFFFFFFFFu, sy, o);
            sz += __shfl_xor_sync(0xFFFFFFFFu, sz, o);
            sw += __shfl_xor_sync(0xFFFFFFFFu, sw, o);
        }
        if (k == 0)
            reinterpret_cast<float4*>(g_u)[g] = make_float4(sx, sy, sz, sw);
    }
}

// ---------------------------------------------------------------------------
// K1 (PDL secondary): 256 threads, 8 warps, 8 tokens/warp, 64 tok/block,
//   grid 2048. 16 front-batched LDG.128 per thread, issued BEFORE the
//   griddep wait on uc. Masked chunks exit before touching anything from uc.
// ---------------------------------------------------------------------------
__global__ void __launch_bounds__(256) energy_exp_kernel(
        const float* __restrict__ q,
        const int* __restrict__ lens) {
    int b     = blockIdx.x >> 5;                 // / 32 blocks per row
    int chunk = blockIdx.x & 31;
    int t0    = chunk * TOK_PER_BLOCK;
    int len   = __ldg(&lens[b]);
    if (t0 >= len) return;                       // masked: no uc data touched

    long rowbase = (long)b * T_DIM;
    int tid  = threadIdx.x;
    int warp = tid >> 5;
    int lane = tid & 31;

    __shared__ float red[TOK_PER_BLOCK];

    int tA = t0 + warp * 8;                      // this warp's 8 tokens

    // issue q loads BEFORE waiting on uc — they don't depend on u
    const float4* qp = reinterpret_cast<const float4*>(q + (rowbase + tA) * H_DIM)
                       + lane * 2;
    float4 z = {0.f, 0.f, 0.f, 0.f};
    float4 r0[8], r1[8];
    bool vld[8];
#pragma unroll
    for (int j = 0; j < 8; ++j) {
        vld[j] = (tA + j) < len;
        const float4* pj = qp + j * (H_DIM / 4);
        r0[j] = vld[j] ? __ldcs(pj)     : z;
        r1[j] = vld[j] ? __ldcs(pj + 1) : z;
    }

    cudaGridDependencySynchronize();             // uc complete; g_u visible

    float4 ua = __ldg(reinterpret_cast<const float4*>(g_u) + lane * 2);
    float4 ub = __ldg(reinterpret_cast<const float4*>(g_u) + lane * 2 + 1);

    float d[8];
#pragma unroll
    for (int j = 0; j < 8; ++j) {
        d[j] = r0[j].x * ua.x + r0[j].y * ua.y + r0[j].z * ua.z + r0[j].w * ua.w
             + r1[j].x * ub.x + r1[j].y * ub.y + r1[j].z * ub.z + r1[j].w * ub.w;
    }
#pragma unroll
    for (int o = 16; o > 0; o >>= 1) {
#pragma unroll
        for (int j = 0; j < 8; ++j) d[j] += __shfl_xor_sync(0xFFFFFFFFu, d[j], o);
    }

    if (lane == 0) {
#pragma unroll
        for (int j = 0; j < 8; ++j) {
            float e = vld[j] ? __expf(d[j]) : 0.f;
            __stcg(&g_exp[rowbase + tA + j], e);
            red[warp * 8 + j] = e;
        }
    }
    __syncthreads();
    if (tid == 0) {
        float s = 0.f;
#pragma unroll
        for (int w = 0; w < TOK_PER_BLOCK; ++w) s += red[w];  // fixed order
        g_psum[blockIdx.x] = s;
    }
}

// ---------------------------------------------------------------------------
// K2 (PDL secondary): 64 blocks x 512 threads. Griddep wait at entry (R11
//   form), then each warp independently reduces the row's 32 psums; one
//   float4 per thread. Masked positions -> exact 0 without loading.
// ---------------------------------------------------------------------------
__global__ void __launch_bounds__(512) scale_kernel(
        const int* __restrict__ lens,
        float* __restrict__ out) {
    int b    = blockIdx.x;
    int tid  = threadIdx.x;
    int lane = tid & 31;
    int len  = __ldg(&lens[b]);
    long rowbase = (long)b * T_DIM;

    cudaGridDependencySynchronize();             // energy complete

    const float* ps = g_psum + b * EBLOCKS_PER_ROW;
    float s = __ldcg(&ps[lane]);                 // 32 psums/row; masked slots = 0
#pragma unroll
    for (int o = 16; o > 0; o >>= 1) s += __shfl_xor_sync(0xFFFFFFFFu, s, o);
    float inv = 1.0f / s;

    int tbase = tid * 4;
    float4* ob = reinterpret_cast<float4*>(out + rowbase);
    if (tbase >= len) {
        ob[tid] = make_float4(0.f, 0.f, 0.f, 0.f);
    } else {
        float4 val = __ldcg(&reinterpret_cast<const float4*>(g_exp + rowbase)[tid]);
        val.x = (tbase + 0 < len) ? val.x * inv : 0.f;
        val.y = (tbase + 1 < len) ? val.y * inv : 0.f;
        val.z = (tbase + 2 < len) ? val.z * inv : 0.f;
        val.w = (tbase + 3 < len) ? val.w * inv : 0.f;
        ob[tid] = val;
    }
}

// ---------------------------------------------------------------------------
extern "C" void kernel_launch(void* const* d_in, const int* in_sizes, int n_in,
                              void* d_out, int out_size) {
    const float* questions = (const float*)d_in[0];   // [B,T,H] f32
    const int*   lens      = (const int*)d_in[1];     // [B] i32
    const float* W         = (const float*)d_in[2];   // [H,H] f32
    // d_in[3] = b (cancels in softmax)
    const float* v         = (const float*)d_in[4];   // [H] f32
    float* out             = (float*)d_out;           // [B,T] f32

    uc_kernel<<<H_DIM / 4, 256>>>(W, v);

    cudaLaunchAttribute attr[1];
    attr[0].id = cudaLaunchAttributeProgrammaticStreamSerialization;
    attr[0].val.programmaticStreamSerializationAllowed = 1;

    {
        cudaLaunchConfig_t cfg = {};
        cfg.gridDim  = dim3(B_DIM * EBLOCKS_PER_ROW);
        cfg.blockDim = dim3(256);
        cfg.attrs = attr;
        cfg.numAttrs = 1;
        cudaLaunchKernelEx(&cfg, energy_exp_kernel, questions, lens);
    }
    {
        cudaLaunchConfig_t cfg = {};
        cfg.gridDim  = dim3(B_DIM);
        cfg.blockDim = dim3(512);
        cfg.attrs = attr;
        cfg.numAttrs = 1;
        cudaLaunchKernelEx(&cfg, scale_kernel, lens, out);
    }
}